// round 17
// baseline (speedup 1.0000x reference)
#include <cuda_runtime.h>
#include <cuda_fp16.h>
#include <cstdint>

#define NUM_USERS 100000
#define NUM_ITEMS 200000
#define NN        (NUM_USERS + NUM_ITEMS)   // 300000
#define D         64
#define UD        (NUM_USERS * D)           // 6400000
#define NNZ       5000000
#define BATCH     16384
#define WIDTH     32                         // ELL width (P(deg>32) ~ 1e-4, spill net)
#define MAX_SPILL 2048
#define FILL_BLOCKS 4883                     // ceil(NNZ/4/256)
#define CONV_BLOCKS 9375                     // NN*D/8/256 exactly

// fp16 embeddings: e0 (converted), layer-1, layer-2 outputs (38.4 MB each)
__device__ __half g_E0[(size_t)NN * D];
__device__ __half g_A[(size_t)NN * D];
__device__ __half g_B[(size_t)NN * D];

// ELL storage: packed (col, val_bits). 76.8 MB (L2-resident)
__device__ int2 g_ell[(size_t)NN * WIDTH];
__device__ int  g_len[NN];

// Spill safety net (degree > WIDTH; expected ~tens of edges)
__device__ int   g_spill_count;
__device__ int   g_srow[MAX_SPILL];
__device__ int   g_scol[MAX_SPILL];
__device__ float g_sval[MAX_SPILL];

// ---------------------------------------------------------------------------
__global__ void init_kernel() {
    int i = blockIdx.x * blockDim.x + threadIdx.x;
    const int n4 = NN / 4;                    // 75000
    if (i < n4)
        reinterpret_cast<int4*>(g_len)[i] = make_int4(0, 0, 0, 0);
    if (i == 0) g_spill_count = 0;
}

// Combined build kernel: blocks [0, FILL_BLOCKS) run ELL fill (atomic-bound),
// blocks [FILL_BLOCKS, +CONV_BLOCKS) run fp32->fp16 convert (DRAM-bound).
__global__ void build_kernel(const int*   __restrict__ erow,
                             const int*   __restrict__ ecol,
                             const float* __restrict__ evals,
                             const float* __restrict__ uemb,
                             const float* __restrict__ iemb) {
    if (blockIdx.x < FILL_BLOCKS) {
        int t = blockIdx.x * blockDim.x + threadIdx.x;
        int i4 = t * 4;
        if (i4 >= NNZ) return;
        int4   r = __ldcs(reinterpret_cast<const int4*>(erow + i4));
        int4   c = __ldcs(reinterpret_cast<const int4*>(ecol + i4));
        float4 v = __ldcs(reinterpret_cast<const float4*>(evals + i4));
        int    rows[4] = {r.x, r.y, r.z, r.w};
        int    cols[4] = {c.x, c.y, c.z, c.w};
        float  vals[4] = {v.x, v.y, v.z, v.w};
#pragma unroll
        for (int k = 0; k < 4; k++) {
            int pos = atomicAdd(&g_len[rows[k]], 1);
            if (pos < WIDTH) {
                g_ell[(size_t)rows[k] * WIDTH + pos] =
                    make_int2(cols[k], __float_as_int(vals[k]));
            } else {
                int s = atomicAdd(&g_spill_count, 1);
                if (s < MAX_SPILL) {
                    g_srow[s] = rows[k]; g_scol[s] = cols[k]; g_sval[s] = vals[k];
                }
            }
        }
    } else {
        long long i8 = ((long long)(blockIdx.x - FILL_BLOCKS) * blockDim.x
                        + threadIdx.x) * 8;
        if (i8 >= (long long)NN * D) return;
        const float* src = (i8 < UD) ? (uemb + i8) : (iemb + (i8 - UD));
        float4 a = *reinterpret_cast<const float4*>(src);
        float4 b = *reinterpret_cast<const float4*>(src + 4);
        __half2 h0 = __floats2half2_rn(a.x, a.y);
        __half2 h1 = __floats2half2_rn(a.z, a.w);
        __half2 h2 = __floats2half2_rn(b.x, b.y);
        __half2 h3 = __floats2half2_rn(b.z, b.w);
        uint4 packed = make_uint4(*reinterpret_cast<uint32_t*>(&h0),
                                  *reinterpret_cast<uint32_t*>(&h1),
                                  *reinterpret_cast<uint32_t*>(&h2),
                                  *reinterpret_cast<uint32_t*>(&h3));
        *reinterpret_cast<uint4*>(g_E0 + i8) = packed;
    }
}

// ---------------------------------------------------------------------------
// Warp computes one output row (round-13 proven body). 16 lanes per edge,
// lane owns dims {4*sub .. 4*sub+3}; halves process alternating edges;
// one cross-half shfl reduce at the end.
// Padding edges carry c=0, v=0: load row 0 (L1-hot), FMA adds 0.
__device__ __forceinline__ float4 spmm_row_acc_h(int node, int lane,
                                                 const __half* __restrict__ src) {
    int n = min(g_len[node], WIDTH);
    int sub  = lane & 15;
    int half_id = lane >> 4;

    int2 ev = make_int2(0, 0);
    if (lane < n)
        ev = __ldcs(g_ell + (size_t)node * WIDTH + lane);  // evict-first stream

    float4 acc = make_float4(0.f, 0.f, 0.f, 0.f);
    int n8 = (n + 7) & ~7;                    // <= 32
    for (int j = 0; j < n8; j += 8) {
#pragma unroll
        for (int k = 0; k < 4; k++) {
            int idx = j + 2 * k + half_id;    // this half's edge
            int   cj = __shfl_sync(0xFFFFFFFFu, ev.x, idx);
            float vj = __int_as_float(__shfl_sync(0xFFFFFFFFu, ev.y, idx));
            uint2 raw = *reinterpret_cast<const uint2*>(
                src + (size_t)cj * D + 4 * sub);
            float2 x0 = __half22float2(*reinterpret_cast<__half2*>(&raw.x));
            float2 x1 = __half22float2(*reinterpret_cast<__half2*>(&raw.y));
            acc.x += vj * x0.x;
            acc.y += vj * x0.y;
            acc.z += vj * x1.x;
            acc.w += vj * x1.y;
        }
    }
    // cross-half reduce: lanes L and L^16 hold partials for the same dims
    acc.x += __shfl_xor_sync(0xFFFFFFFFu, acc.x, 16);
    acc.y += __shfl_xor_sync(0xFFFFFFFFu, acc.y, 16);
    acc.z += __shfl_xor_sync(0xFFFFFFFFu, acc.z, 16);
    acc.w += __shfl_xor_sync(0xFFFFFFFFu, acc.w, 16);
    return acc;
}

// Rare-path (post-reduce): add spill contributions for rows deg > WIDTH.
__device__ __forceinline__ float4 spill_patch_h(int node, int lane, float4 acc,
                                                const __half* __restrict__ src) {
    if (g_len[node] > WIDTH) {                 // ~25 rows in the whole graph
        int sub = lane & 15;
        int cnt = min(g_spill_count, MAX_SPILL);
        for (int s = 0; s < cnt; s++) {
            if (g_srow[s] == node) {
                int   cj = g_scol[s];
                float vj = g_sval[s];
                uint2 raw = *reinterpret_cast<const uint2*>(
                    src + (size_t)cj * D + 4 * sub);
                float2 x0 = __half22float2(*reinterpret_cast<__half2*>(&raw.x));
                float2 x1 = __half22float2(*reinterpret_cast<__half2*>(&raw.y));
                acc.x += vj * x0.x;
                acc.y += vj * x0.y;
                acc.z += vj * x1.x;
                acc.w += vj * x1.y;
            }
        }
    }
    return acc;
}

// Full SpMM (layers 1, 2): one warp per destination row; lanes<16 store 8B each.
__global__ void spmm_ell_kernel(int stage) {
    int warp = (blockIdx.x * blockDim.x + threadIdx.x) >> 5;
    int lane = threadIdx.x & 31;
    if (warp >= NN) return;

    const __half* src = (stage == 0) ? g_E0 : g_A;
    __half*       dst = (stage == 0) ? g_A  : g_B;

    float4 acc = spmm_row_acc_h(warp, lane, src);

    if (lane < 16) {
        __half2 h0 = __floats2half2_rn(acc.x, acc.y);
        __half2 h1 = __floats2half2_rn(acc.z, acc.w);
        uint32_t b0 = *reinterpret_cast<uint32_t*>(&h0);
        uint32_t b1 = *reinterpret_cast<uint32_t*>(&h1);
        asm volatile("st.global.cs.v2.b32 [%0], {%1, %2};"
                     :: "l"(dst + (size_t)warp * D + 4 * lane), "r"(b0), "r"(b1)
                     : "memory");
    }
}

// Spill mop-up (tiny grid, usually no-op): 16 threads/edge, 4 dims each.
__global__ void spill_kernel(int stage) {
    int cnt = min(g_spill_count, MAX_SPILL);
    int idx = blockIdx.x * blockDim.x + threadIdx.x;
    int e = idx >> 4;
    int q = idx & 15;
    if (e >= cnt) return;

    const __half* src = (stage == 0) ? g_E0 : g_A;
    __half*       dst = (stage == 0) ? g_A  : g_B;

    int   row = g_srow[e];
    int   col = g_scol[e];
    float v   = g_sval[e];
    const __half* srow = src + (size_t)col * D + q * 4;
    __half* p = dst + (size_t)row * D + q * 4;
#pragma unroll
    for (int h = 0; h < 2; h++) {
        uint32_t raw = *reinterpret_cast<const uint32_t*>(srow + 2 * h);
        float2 x = __half22float2(*reinterpret_cast<__half2*>(&raw));
        __half2 m = __floats2half2_rn(v * x.x, v * x.y);
        uint32_t mb = *reinterpret_cast<uint32_t*>(&m);
        asm volatile("red.global.add.noftz.f16x2 [%0], %1;"
                     :: "l"(p + 2 * h), "r"(mb) : "memory");
    }
}

// ---------------------------------------------------------------------------
// Fused layer-3 + dot: TWO warps per pair (one per endpoint) — halves the
// serial e3 gather chain. 256 threads = 8 warps = 4 pairs per block.
// Warp (pair_in_blk, side): side 0 = user endpoint, side 1 = item endpoint.
// Each warp computes full (e0+e1+e2+e3) vector into smem; 4 warps do dots.
__global__ void final_kernel(const int*   __restrict__ users,
                             const int*   __restrict__ items,
                             const float* __restrict__ uemb,
                             const float* __restrict__ iemb,
                             float*       __restrict__ out) {
    __shared__ float4 s_vec[4][2][16];

    int tid  = threadIdx.x;
    int wid  = tid >> 5;          // 0..7
    int lane = tid & 31;
    int pib  = wid & 3;           // pair within block: 0..3
    int side = wid >> 2;          // 0 = user, 1 = item
    int pair = blockIdx.x * 4 + pib;   // BATCH divisible by 4

    int node;
    const float* e0base;
    if (side == 0) {
        int u = __ldg(users + pair);
        node = u;
        e0base = uemb + (size_t)u * D;
    } else {
        int it = __ldg(items + pair);
        node = NUM_USERS + it;
        e0base = iemb + (size_t)it * D;
    }

    // e3 at this endpoint (layer-3 SpMM, inline, fp16 gathers)
    float4 e3 = spmm_row_acc_h(node, lane, g_B);
    e3 = spill_patch_h(node, lane, e3, g_B);

    if (lane < 16) {
        int sub = lane;
        size_t row = (size_t)node * D + 4 * sub;
        uint2 ra = *reinterpret_cast<const uint2*>(g_A + row);
        uint2 rb = *reinterpret_cast<const uint2*>(g_B + row);
        float4 e0 = *reinterpret_cast<const float4*>(e0base + 4 * sub);

        float2 a0 = __half22float2(*reinterpret_cast<__half2*>(&ra.x));
        float2 a1 = __half22float2(*reinterpret_cast<__half2*>(&ra.y));
        float2 b0 = __half22float2(*reinterpret_cast<__half2*>(&rb.x));
        float2 b1 = __half22float2(*reinterpret_cast<__half2*>(&rb.y));

        float4 v;
        v.x = e0.x + a0.x + b0.x + e3.x;
        v.y = e0.y + a0.y + b0.y + e3.y;
        v.z = e0.z + a1.x + b1.x + e3.z;
        v.w = e0.w + a1.y + b1.y + e3.w;
        s_vec[pib][side][sub] = v;
    }
    __syncthreads();

    // First 4 warps: dot product for their pair
    if (wid < 4) {
        float dot = 0.f;
        if (lane < 16) {
            float4 uv = s_vec[wid][0][lane];
            float4 iv = s_vec[wid][1][lane];
            dot = uv.x * iv.x + uv.y * iv.y + uv.z * iv.z + uv.w * iv.w;
        }
#pragma unroll
        for (int off = 16; off > 0; off >>= 1)
            dot += __shfl_xor_sync(0xFFFFFFFFu, dot, off);
        if (lane == 0) out[blockIdx.x * 4 + wid] = dot * 0.0625f;  // (1/4)*(1/4)
    }
}

// ---------------------------------------------------------------------------
extern "C" void kernel_launch(void* const* d_in, const int* in_sizes, int n_in,
                              void* d_out, int out_size) {
    const int*   users = (const int*)  d_in[0];
    const int*   items = (const int*)  d_in[1];
    const int*   erow  = (const int*)  d_in[2];
    const int*   ecol  = (const int*)  d_in[3];
    const float* evals = (const float*)d_in[4];
    const float* uemb  = (const float*)d_in[5];
    const float* iemb  = (const float*)d_in[6];
    float* out = (float*)d_out;

    // --- init, then overlapped ELL fill + fp16 convert ---
    init_kernel<<<(NN / 4 + 255) / 256, 256>>>();
    build_kernel<<<FILL_BLOCKS + CONV_BLOCKS, 256>>>(erow, ecol, evals, uemb, iemb);

    int threads = 256;                         // 8 warps/block
    int blocks  = (NN + 7) / 8;                // 37500
    int sblocks = (MAX_SPILL * 16) / 256;      // 128

    // --- layers 1,2 full; layer 3 fused into final ---
    spmm_ell_kernel<<<blocks, threads>>>(0);
    spill_kernel<<<sblocks, 256>>>(0);

    spmm_ell_kernel<<<blocks, threads>>>(1);
    spill_kernel<<<sblocks, 256>>>(1);

    // --- fused layer-3 + gather + dot (2 warps per pair) ---
    final_kernel<<<BATCH / 4, 256>>>(users, items, uemb, iemb, out);
}